// round 6
// baseline (speedup 1.0000x reference)
#include <cuda_runtime.h>
#include <cuda_bf16.h>
#include <math.h>
#include <stdint.h>

#define NR 4096      // B*T
#define DY 784
#define DH 400
#define KS 16
#define LD 16
#define BBAT 32
#define TT 128

// ======================= device scratch =====================================
__device__ float g_h[NR * DH];                       // encoder hidden
__device__ float g_base[NR * DH];                    // base [n][h]
__device__ float g_logb[NR * KS];                    // log b_k
__device__ __align__(16) uint32_t g_Bhi2[896 * 200]; // dec_w bf16-hi, padded rows
__device__ __align__(16) uint32_t g_Blo2[896 * 200];
__device__ __align__(16) uint32_t g_W1hi[448 * 392]; // enc_w1 bf16-hi, padded rows
__device__ __align__(16) uint32_t g_W1lo[448 * 392];
__device__ __align__(16) uint32_t g_Yhi[NR * 392];   // y bf16-hi
__device__ __align__(16) uint32_t g_Ylo[NR * 392];

// ======================= helpers ============================================
__device__ __forceinline__ uint32_t smem_u32(const void* p) {
    uint32_t a;
    asm("{ .reg .u64 t; cvta.to.shared.u64 t, %1; cvt.u32.u64 %0, t; }" : "=r"(a) : "l"(p));
    return a;
}
__device__ __forceinline__ void ldsm_x4(uint32_t* r, uint32_t addr) {
    asm volatile("ldmatrix.sync.aligned.m8n8.x4.shared.b16 {%0,%1,%2,%3}, [%4];"
                 : "=r"(r[0]), "=r"(r[1]), "=r"(r[2]), "=r"(r[3]) : "r"(addr));
}
__device__ __forceinline__ void ldsm_x2(uint32_t* r, uint32_t addr) {
    asm volatile("ldmatrix.sync.aligned.m8n8.x2.shared.b16 {%0,%1}, [%2];"
                 : "=r"(r[0]), "=r"(r[1]) : "r"(addr));
}
__device__ __forceinline__ void mma_bf16(float* c, const uint32_t* a, const uint32_t* b) {
    asm volatile("mma.sync.aligned.m16n8k16.row.col.f32.bf16.bf16.f32 "
                 "{%0,%1,%2,%3}, {%4,%5,%6,%7}, {%8,%9}, {%0,%1,%2,%3};"
                 : "+f"(c[0]), "+f"(c[1]), "+f"(c[2]), "+f"(c[3])
                 : "r"(a[0]), "r"(a[1]), "r"(a[2]), "r"(a[3]), "r"(b[0]), "r"(b[1]));
}
__device__ __forceinline__ uint32_t pack_hi_lo(float v0, float v1, uint32_t& lo_out) {
    __nv_bfloat16 h0 = __float2bfloat16(v0);
    __nv_bfloat16 h1 = __float2bfloat16(v1);
    __nv_bfloat16 l0 = __float2bfloat16(v0 - __bfloat162float(h0));
    __nv_bfloat16 l1 = __float2bfloat16(v1 - __bfloat162float(h1));
    lo_out = (uint32_t)__bfloat16_as_ushort(l0) | ((uint32_t)__bfloat16_as_ushort(l1) << 16);
    return (uint32_t)__bfloat16_as_ushort(h0) | ((uint32_t)__bfloat16_as_ushort(h1) << 16);
}
__device__ __forceinline__ float bce_term(float s, float y) {
    float e = __expf(-fabsf(s));
    float l0 = -__logf(1.f + e);
    float lp = fmaxf(l0 + fminf(s, 0.f), -100.f);
    float l1 = fmaxf(l0 - fmaxf(s, 0.f), -100.f);
    return -(y * lp + (1.f - y) * l1);
}

// ======================= prep: fp32 -> bf16 hi/lo ===========================
// ranges: [0,179200) dec_w -> Bhi2[896][200]; [179200, 354816) w1 -> W1hi[448][392];
//         [354816, 1960448) y -> Yhi[4096][392]
__global__ void prep_kernel(const float* __restrict__ dec_w,
                            const float* __restrict__ enc_w1,
                            const float* __restrict__ y_flat) {
    int e = blockIdx.x * 256 + threadIdx.x;
    if (e < 179200) {
        int row = e / 200, c = e - row * 200;
        float2 v = (row < DY) ? *(const float2*)&dec_w[row * DH + 2 * c]
                              : make_float2(0.f, 0.f);
        uint32_t lo, hi = pack_hi_lo(v.x, v.y, lo);
        g_Bhi2[e] = hi; g_Blo2[e] = lo;
    } else if (e < 354816) {
        int e2 = e - 179200;
        int row = e2 / 392, c = e2 - row * 392;
        float2 v = (row < DH) ? *(const float2*)&enc_w1[row * DY + 2 * c]
                              : make_float2(0.f, 0.f);
        uint32_t lo, hi = pack_hi_lo(v.x, v.y, lo);
        g_W1hi[e2] = hi; g_W1lo[e2] = lo;
    } else {
        int e3 = e - 354816;
        if (e3 < NR * 392) {
            int row = e3 / 392, c = e3 - row * 392;
            float2 v = *(const float2*)&y_flat[row * DY + 2 * c];
            uint32_t lo, hi = pack_hi_lo(v.x, v.y, lo);
            g_Yhi[e3] = hi; g_Ylo[e3] = lo;
        }
    }
}

// ======================= gemm1: h = relu(y @ W1^T + b1), bf16x3 mma =========
// grid (32 m-tiles of 128, 4 o-chunks of 112), 256 threads = 4 rowgrp x 2 colgrp
#define G1_A_HI 0
#define G1_A_LO 30720           // 128*240
#define G1_B_HI 61440
#define G1_B_LO 88320           // +112*240
#define G1_SMEM 115200

__global__ void gemm1_mma_kernel(const float* __restrict__ b1) {
    extern __shared__ char smem[];
    uint32_t sb = smem_u32(smem);
    int tid = threadIdx.x;
    int w = tid >> 5, lane = tid & 31;
    int mw = w & 3, cg = w >> 2;
    int n0 = blockIdx.x * 128;
    int o0 = blockIdx.y * 112;
    int l15 = lane & 15;

    uint32_t aAddr = sb + G1_A_HI + (uint32_t)(mw * 32 + l15) * 240
                     + (uint32_t)((lane >> 4) & 1) * 16;
    uint32_t bAddrP = sb + G1_B_HI + (uint32_t)(cg * 56 + ((lane >> 4) & 1) * 8 + (lane & 7)) * 240
                      + (uint32_t)((lane >> 3) & 1) * 16;
    uint32_t bAddr6 = sb + G1_B_HI + (uint32_t)(cg * 56 + 48 + (l15 & 7)) * 240
                      + (uint32_t)(l15 >> 3) * 16;

    float acc[2][7][4];
#pragma unroll
    for (int mi = 0; mi < 2; mi++)
#pragma unroll
        for (int nf = 0; nf < 7; nf++)
#pragma unroll
            for (int c = 0; c < 4; c++) acc[mi][nf][c] = 0.f;

    for (int kc = 0; kc < 7; kc++) {
        // A tile copy: [128][112] hi/lo from g_Yhi/g_Ylo
        for (int t = tid; t < 1792; t += 256) {
            int row = t / 14, q = t - row * 14;
            uint32_t dst = (uint32_t)row * 240 + (uint32_t)q * 16;
            size_t src = (size_t)(n0 + row) * 98 + kc * 14 + q;
            *(uint4*)(smem + G1_A_HI + dst) = ((const uint4*)g_Yhi)[src];
            *(uint4*)(smem + G1_A_LO + dst) = ((const uint4*)g_Ylo)[src];
        }
        // B tile copy: [112][112] from g_W1hi/lo
        for (int t = tid; t < 1568; t += 256) {
            int row = t / 14, q = t - row * 14;
            uint32_t dst = (uint32_t)row * 240 + (uint32_t)q * 16;
            size_t src = (size_t)(o0 + row) * 98 + kc * 14 + q;
            *(uint4*)(smem + G1_B_HI + dst) = ((const uint4*)g_W1hi)[src];
            *(uint4*)(smem + G1_B_LO + dst) = ((const uint4*)g_W1lo)[src];
        }
        __syncthreads();
#pragma unroll
        for (int ks = 0; ks < 7; ks++) {
            uint32_t ah[2][4], al[2][4];
#pragma unroll
            for (int mi = 0; mi < 2; mi++) {
                uint32_t a = aAddr + (uint32_t)mi * (16 * 240) + (uint32_t)ks * 32;
                ldsm_x4(ah[mi], a);
                ldsm_x4(al[mi], a + (G1_A_LO - G1_A_HI));
            }
            uint32_t bh[7][2], bl[7][2];
#pragma unroll
            for (int p = 0; p < 3; p++) {
                uint32_t b = bAddrP + (uint32_t)p * (16 * 240) + (uint32_t)ks * 32;
                uint32_t t4[4];
                ldsm_x4(t4, b);
                bh[2 * p][0] = t4[0]; bh[2 * p][1] = t4[1];
                bh[2 * p + 1][0] = t4[2]; bh[2 * p + 1][1] = t4[3];
                ldsm_x4(t4, b + (G1_B_LO - G1_B_HI));
                bl[2 * p][0] = t4[0]; bl[2 * p][1] = t4[1];
                bl[2 * p + 1][0] = t4[2]; bl[2 * p + 1][1] = t4[3];
            }
            {
                uint32_t b = bAddr6 + (uint32_t)ks * 32;
                ldsm_x2(bh[6], b);
                ldsm_x2(bl[6], b + (G1_B_LO - G1_B_HI));
            }
#pragma unroll
            for (int nf = 0; nf < 7; nf++)
#pragma unroll
                for (int mi = 0; mi < 2; mi++) {
                    mma_bf16(acc[mi][nf], ah[mi], bh[nf]);
                    mma_bf16(acc[mi][nf], ah[mi], bl[nf]);
                    mma_bf16(acc[mi][nf], al[mi], bh[nf]);
                }
        }
        __syncthreads();
    }
    // epilogue: relu(acc + b1) -> g_h
#pragma unroll
    for (int mi = 0; mi < 2; mi++) {
        int r0 = n0 + mw * 32 + mi * 16 + (lane >> 2);
#pragma unroll
        for (int nf = 0; nf < 7; nf++) {
            int h = o0 + cg * 56 + nf * 8 + 2 * (lane & 3);
            if (h < DH) {
                float2 bb = *(const float2*)&b1[h];
                g_h[r0 * DH + h]           = fmaxf(acc[mi][nf][0] + bb.x, 0.f);
                g_h[r0 * DH + h + 1]       = fmaxf(acc[mi][nf][1] + bb.y, 0.f);
                g_h[(r0 + 8) * DH + h]     = fmaxf(acc[mi][nf][2] + bb.x, 0.f);
                g_h[(r0 + 8) * DH + h + 1] = fmaxf(acc[mi][nf][3] + bb.y, 0.f);
            }
        }
    }
}

// ======================= enc2 + reparam + base (fused) ======================
// dyn smem floats: sh_h[16][401]@0, sw[32][65]@6416, sml[16][32]@8496,
//                  wz[400*17]@9008, z[16][16]@15808  (total 16064 floats)
__global__ void enc2base_kernel(const float* __restrict__ w2, const float* __restrict__ b2,
                                const float* __restrict__ eps,
                                const float* __restrict__ dec_fc_w,
                                const float* __restrict__ dec_fc_b) {
    extern __shared__ float sm[];
    float* sh_h = sm;
    float* sw   = sm + 6416;
    float* sml  = sm + 8496;
    float* wz   = sm + 9008;
    float* zsh  = sm + 15808;
    int n0 = blockIdx.x * 16;
    int tid = threadIdx.x;

    for (int e = tid; e < 16 * DH; e += 256) {
        int r = e / DH, l = e - r * DH;
        sh_h[r * 401 + l] = g_h[(n0 + r) * DH + l];
    }
    for (int i = tid; i < 6400; i += 256)
        wz[(i >> 4) * 17 + (i & 15)] = dec_fc_w[(i >> 4) * 32 + (i & 15)];

    int r0 = tid >> 5, jj = tid & 31;
    float a0 = b2[jj], a1 = b2[jj];
    for (int l0 = 0; l0 < DH; l0 += 64) {
        int wd = min(64, DH - l0);
        for (int e = tid; e < 32 * 64; e += 256) {
            int j = e >> 6, ll = e & 63;
            if (ll < wd) sw[j * 65 + ll] = w2[j * DH + l0 + ll];
        }
        __syncthreads();
        for (int ll = 0; ll < wd; ll++) {
            float wv = sw[jj * 65 + ll];
            a0 = fmaf(sh_h[r0 * 401 + l0 + ll], wv, a0);
            a1 = fmaf(sh_h[(r0 + 8) * 401 + l0 + ll], wv, a1);
        }
        __syncthreads();
    }
    sml[r0 * 32 + jj] = a0;
    sml[(r0 + 8) * 32 + jj] = a1;
    __syncthreads();
    {
        int r = tid >> 4, l = tid & 15;
        float mu = sml[r * 32 + l], lv = sml[r * 32 + 16 + l];
        zsh[r * 16 + l] = fmaf(eps[(n0 + r) * LD + l], __expf(0.5f * lv), mu);
    }
    __syncthreads();
    // base rows for this n block
#pragma unroll
    for (int i = 0; i < 25; i++) {
        int idx = tid + i * 256;
        int n = idx / DH, h = idx - n * DH;
        float acc = dec_fc_b[h];
        const float* zr = &zsh[n * 16];
        const float* wr = &wz[h * 17];
#pragma unroll
        for (int l = 0; l < 16; l++) acc = fmaf(zr[l], wr[l], acc);
        g_base[(n0 + n) * DH + h] = acc;
    }
}

// ======================= bk: resident-A bf16x3 mma + fused BCE ==============
// grid (64 m-tiles of 64, 16 comps), 256 threads = 2 rowgrp(32) x 4 colgrp(32)
// A [64][400] hi/lo resident (pitch 408 elem = 816B). B double-buffered
// [128 o][80 k] tiles (pitch 88 elem = 176B).
#define BK_A_HI 0
#define BK_A_LO 52224            // 64*816
#define BK_B0   104448
#define BK_BSZ  45056            // per buffer: hi 22528 + lo 22528
#define BK_BLO  22528
#define BK_WX   194560           // 400 floats
#define BK_PART 196160           // 4*64 floats
#define BK_SMEM 197184

__global__ void bk_kernel(const float* __restrict__ dec_fc_w,
                          const float* __restrict__ dec_b,
                          const float* __restrict__ y_flat) {
    extern __shared__ char smem[];
    uint32_t sb = smem_u32(smem);
    int tid = threadIdx.x;
    int w = tid >> 5, lane = tid & 31;
    int k = blockIdx.y;
    int n0 = blockIdx.x * 64;
    int rg = w & 1, cg = w >> 1;
    int l15 = lane & 15;

    float* wxp = (float*)(smem + BK_WX);
    for (int i = tid; i < DH; i += 256) wxp[i] = dec_fc_w[i * 32 + LD + k];
    __syncthreads();

    // build A once: relu(base + wx) -> bf16 hi/lo
#pragma unroll
    for (int i = 0; i < 50; i++) {
        int e = tid + i * 256;           // 64 rows x 200 uint32
        int row = e / 200, c = e - row * 200;
        int h = 2 * c;
        float2 bv = *(const float2*)&g_base[(n0 + row) * DH + h];
        float a0 = fmaxf(bv.x + wxp[h], 0.f);
        float a1 = fmaxf(bv.y + wxp[h + 1], 0.f);
        uint32_t lo, hi = pack_hi_lo(a0, a1, lo);
        uint32_t off = (uint32_t)row * 816 + (uint32_t)c * 4;
        *(uint32_t*)(smem + BK_A_HI + off) = hi;
        *(uint32_t*)(smem + BK_A_LO + off) = lo;
    }

    uint32_t aAddr = sb + BK_A_HI + (uint32_t)(rg * 32 + l15) * 816
                     + (uint32_t)((lane >> 4) & 1) * 16;
    uint32_t bAddrP = (uint32_t)(cg * 32 + ((lane >> 4) & 1) * 8 + (lane & 7)) * 176
                      + (uint32_t)((lane >> 3) & 1) * 16;

    // prologue: copy tile 0 (oc=0, kc=0) into buffer 0
    {
        for (int t = tid; t < 1280; t += 256) {
            int row = t / 10, q = t - row * 10;
            uint32_t dst = (uint32_t)row * 176 + (uint32_t)q * 16;
            size_t src = (size_t)row * 50 + q;
            *(uint4*)(smem + BK_B0 + dst) = ((const uint4*)g_Bhi2)[src];
            *(uint4*)(smem + BK_B0 + BK_BLO + dst) = ((const uint4*)g_Blo2)[src];
        }
    }
    __syncthreads();

    float rec[4] = {0.f, 0.f, 0.f, 0.f};
    float acc[2][4][4];
#pragma unroll
    for (int mi = 0; mi < 2; mi++)
#pragma unroll
        for (int nf = 0; nf < 4; nf++)
#pragma unroll
            for (int c = 0; c < 4; c++) acc[mi][nf][c] = 0.f;

    for (int t = 0; t < 35; t++) {
        int oc = t / 5, kc = t - oc * 5;
        uint32_t bufc = sb + BK_B0 + (uint32_t)(t & 1) * BK_BSZ;
        // prefetch next tile into the other buffer
        if (t < 34) {
            int tn = t + 1;
            int ocn = tn / 5, kcn = tn - ocn * 5;
            char* dstb = smem + BK_B0 + ((tn & 1) * BK_BSZ);
            for (int tt = tid; tt < 1280; tt += 256) {
                int row = tt / 10, q = tt - row * 10;
                uint32_t dst = (uint32_t)row * 176 + (uint32_t)q * 16;
                size_t src = (size_t)(ocn * 128 + row) * 50 + kcn * 10 + q;
                *(uint4*)(dstb + dst) = ((const uint4*)g_Bhi2)[src];
                *(uint4*)(dstb + BK_BLO + dst) = ((const uint4*)g_Blo2)[src];
            }
        }
        // MMA on current tile
#pragma unroll
        for (int ks = 0; ks < 5; ks++) {
            uint32_t kb = (uint32_t)(kc * 160 + ks * 32);
            uint32_t ah[2][4], al[2][4];
#pragma unroll
            for (int mi = 0; mi < 2; mi++) {
                uint32_t a = aAddr + (uint32_t)mi * (16 * 816) + kb;
                ldsm_x4(ah[mi], a);
                ldsm_x4(al[mi], a + (BK_A_LO - BK_A_HI));
            }
            uint32_t bh[4][2], bl[4][2];
#pragma unroll
            for (int p = 0; p < 2; p++) {
                uint32_t b = bufc + bAddrP + (uint32_t)p * (16 * 176) + (uint32_t)ks * 32;
                uint32_t t4[4];
                ldsm_x4(t4, b);
                bh[2 * p][0] = t4[0]; bh[2 * p][1] = t4[1];
                bh[2 * p + 1][0] = t4[2]; bh[2 * p + 1][1] = t4[3];
                ldsm_x4(t4, b + BK_BLO);
                bl[2 * p][0] = t4[0]; bl[2 * p][1] = t4[1];
                bl[2 * p + 1][0] = t4[2]; bl[2 * p + 1][1] = t4[3];
            }
#pragma unroll
            for (int nf = 0; nf < 4; nf++)
#pragma unroll
                for (int mi = 0; mi < 2; mi++) {
                    mma_bf16(acc[mi][nf], ah[mi], bh[nf]);
                    mma_bf16(acc[mi][nf], ah[mi], bl[nf]);
                    mma_bf16(acc[mi][nf], al[mi], bh[nf]);
                }
        }
        // epilogue when a full o-chunk completes
        if (kc == 4) {
            int o0 = oc * 128;
#pragma unroll
            for (int mi = 0; mi < 2; mi++) {
                int r0 = n0 + rg * 32 + mi * 16 + (lane >> 2);
#pragma unroll
                for (int nf = 0; nf < 4; nf++) {
                    int col = o0 + cg * 32 + nf * 8 + 2 * (lane & 3);
                    if (col < DY) {
                        float2 db = *(const float2*)&dec_b[col];
                        float2 y0 = *(const float2*)&y_flat[(size_t)r0 * DY + col];
                        float2 y1 = *(const float2*)&y_flat[(size_t)(r0 + 8) * DY + col];
                        rec[mi * 2 + 0] += bce_term(acc[mi][nf][0] + db.x, y0.x)
                                         + bce_term(acc[mi][nf][1] + db.y, y0.y);
                        rec[mi * 2 + 1] += bce_term(acc[mi][nf][2] + db.x, y1.x)
                                         + bce_term(acc[mi][nf][3] + db.y, y1.y);
                    }
                    acc[mi][nf][0] = acc[mi][nf][1] = acc[mi][nf][2] = acc[mi][nf][3] = 0.f;
                }
            }
        }
        __syncthreads();
    }

    // reduce: quad lanes hold same rows
#pragma unroll
    for (int i = 0; i < 4; i++) {
        rec[i] += __shfl_xor_sync(0xffffffffu, rec[i], 1);
        rec[i] += __shfl_xor_sync(0xffffffffu, rec[i], 2);
    }
    float* part = (float*)(smem + BK_PART);
    if ((lane & 3) == 0) {
        int q = lane >> 2;
#pragma unroll
        for (int mi = 0; mi < 2; mi++) {
            part[cg * 64 + rg * 32 + mi * 16 + q]     = rec[mi * 2 + 0];
            part[cg * 64 + rg * 32 + mi * 16 + 8 + q] = rec[mi * 2 + 1];
        }
    }
    __syncthreads();
    if (tid < 64) {
        float s = part[tid] + part[64 + tid] + part[128 + tid] + part[192 + tid];
        g_logb[(n0 + tid) * KS + k] = -s * 0.01f;
    }
}

// ======================= HMM forward-backward + gamma/xi ====================
__global__ void hmm_kernel(const float* __restrict__ log_pi, const float* __restrict__ log_A,
                           float* __restrict__ out) {
    __shared__ float lA[16][17];
    __shared__ float lp[16];
    __shared__ float lb[TT][16];
    __shared__ float al[TT][16];
    __shared__ float be[TT][16];
    __shared__ float s_llik;
    int b = blockIdx.x;
    int tid = threadIdx.x;

    for (int e = tid; e < TT * 16; e += 256) ((float*)lb)[e] = g_logb[b * (TT * 16) + e];

    if (tid < 16) {
        int j = tid;
        float x[16], m = -1e30f;
#pragma unroll
        for (int k2 = 0; k2 < 16; k2++) { x[k2] = log_A[j * 16 + k2]; m = fmaxf(m, x[k2]); }
        float s = 0.f;
#pragma unroll
        for (int k2 = 0; k2 < 16; k2++) s += expf(x[k2] - m);
        float inv = 1.f / s;
#pragma unroll
        for (int k2 = 0; k2 < 16; k2++) lA[j][k2] = logf(expf(x[k2] - m) * inv + 1e-9f);
    } else if (tid == 16) {
        float x[16], m = -1e30f;
#pragma unroll
        for (int k2 = 0; k2 < 16; k2++) { x[k2] = log_pi[k2]; m = fmaxf(m, x[k2]); }
        float s = 0.f;
#pragma unroll
        for (int k2 = 0; k2 < 16; k2++) s += expf(x[k2] - m);
        float inv = 1.f / s;
#pragma unroll
        for (int k2 = 0; k2 < 16; k2++) lp[k2] = logf(expf(x[k2] - m) * inv + 1e-9f);
    }
    __syncthreads();

    int warp = tid >> 5, lane = tid & 31;
    if (warp == 0 && lane < 16) {
        int k = lane;
        al[0][k] = lp[k] + lb[0][k];
        __syncwarp(0xffffu);
        for (int t = 1; t < TT; t++) {
            float m = -1e30f;
#pragma unroll
            for (int j = 0; j < 16; j++) m = fmaxf(m, al[t - 1][j] + lA[j][k]);
            float s = 0.f;
#pragma unroll
            for (int j = 0; j < 16; j++) s += expf(al[t - 1][j] + lA[j][k] - m);
            al[t][k] = m + logf(s) + lb[t][k];
            __syncwarp(0xffffu);
        }
        float v = al[TT - 1][k];
        float mm = v;
#pragma unroll
        for (int off = 8; off > 0; off >>= 1) mm = fmaxf(mm, __shfl_xor_sync(0xffffu, mm, off, 16));
        float se = expf(v - mm);
#pragma unroll
        for (int off = 8; off > 0; off >>= 1) se += __shfl_xor_sync(0xffffu, se, off, 16);
        if (k == 0) s_llik = mm + logf(se);
    } else if (warp == 1 && lane < 16) {
        int j = lane;
        be[TT - 1][j] = 0.f;
        __syncwarp(0xffffu);
        for (int t = TT - 2; t >= 0; t--) {
            float m = -1e30f;
#pragma unroll
            for (int k2 = 0; k2 < 16; k2++)
                m = fmaxf(m, lA[j][k2] + lb[t + 1][k2] + be[t + 1][k2]);
            float s = 0.f;
#pragma unroll
            for (int k2 = 0; k2 < 16; k2++)
                s += expf(lA[j][k2] + lb[t + 1][k2] + be[t + 1][k2] - m);
            be[t][j] = m + logf(s);
            __syncwarp(0xffffu);
        }
    }
    __syncthreads();
    float llik = s_llik;

    float* outg = out + b * (TT * 16);
    for (int e = tid; e < TT * 16; e += 256) {
        int t = e >> 4, k = e & 15;
        outg[e] = expf(al[t][k] + be[t][k] - llik);
    }
    float* outx = out + BBAT * TT * 16 + (long)b * (TT - 1) * 256;
    int j = tid >> 4, k = tid & 15;
    float lajk = lA[j][k];
    for (int t = 0; t < TT - 1; t++) {
        float v = al[t][j] + lajk + lb[t + 1][k] + be[t + 1][k] - llik;
        outx[t * 256 + tid] = expf(v);
    }
}

// ======================= launch =============================================
extern "C" void kernel_launch(void* const* d_in, const int* in_sizes, int n_in,
                              void* d_out, int out_size) {
    const float* y_batch  = (const float*)d_in[0];
    const float* enc_w1   = (const float*)d_in[1];
    const float* enc_b1   = (const float*)d_in[2];
    const float* enc_w2   = (const float*)d_in[3];
    const float* enc_b2   = (const float*)d_in[4];
    const float* dec_fc_w = (const float*)d_in[5];
    const float* dec_fc_b = (const float*)d_in[6];
    const float* dec_w    = (const float*)d_in[7];
    const float* dec_b    = (const float*)d_in[8];
    const float* log_pi   = (const float*)d_in[9];
    const float* log_A    = (const float*)d_in[10];
    const float* eps      = (const float*)d_in[11];
    float* out = (float*)d_out;

    static int configured = 0;
    if (!configured) {
        cudaFuncSetAttribute(gemm1_mma_kernel, cudaFuncAttributeMaxDynamicSharedMemorySize, G1_SMEM);
        cudaFuncSetAttribute(enc2base_kernel, cudaFuncAttributeMaxDynamicSharedMemorySize, 16064 * 4);
        cudaFuncSetAttribute(bk_kernel, cudaFuncAttributeMaxDynamicSharedMemorySize, BK_SMEM);
        configured = 1;
    }

    prep_kernel<<<7658, 256>>>(dec_w, enc_w1, y_batch);                       // idx 0
    gemm1_mma_kernel<<<dim3(32, 4), 256, G1_SMEM>>>(enc_b1);                  // idx 1
    enc2base_kernel<<<256, 256, 16064 * 4>>>(enc_w2, enc_b2, eps,
                                             dec_fc_w, dec_fc_b);             // idx 2
    bk_kernel<<<dim3(64, KS), 256, BK_SMEM>>>(dec_fc_w, dec_b, y_batch);      // idx 3
    hmm_kernel<<<BBAT, 256>>>(log_pi, log_A, out);                            // idx 4
}